// round 2
// baseline (speedup 1.0000x reference)
#include <cuda_runtime.h>
#include <math.h>
#include <math_constants.h>

#define NN 20000
#define EE 160000
#define DD 128

// ---------------- scratch (static device globals; no allocation) ----------------
__device__ float g_q[NN * 512];
__device__ float g_k[NN * 512];
__device__ float g_v[NN * 512];
__device__ float g_skip[NN * DD];
__device__ float g_alpha[EE * 4];   // alpha, then overwritten with exp values
__device__ float g_m[NN * 4];
__device__ float g_den[NN * 4];
__device__ float g_agg[NN * 512];
__device__ float g_x1[NN * DD];
__device__ float g_tv[NN * DD];
__device__ float g_tout[NN * DD];
__device__ float g_x2[NN * DD];
__device__ float g_h[NN * 512];
__device__ float g_ffn[NN * DD];

// ---------------- init: m=-inf, den=0, agg=0 ----------------
__global__ void init_kernel() {
    int idx = blockIdx.x * blockDim.x + threadIdx.x;
    if (idx < NN * 512) g_agg[idx] = 0.f;
    if (idx < NN * 4) { g_m[idx] = -CUDART_INF_F; g_den[idx] = 0.f; }
}

// ---------------- generic fp32 GEMM: C[M,Nc] = A[M,K] @ W[Nc,K]^T + bias ----------------
// 64x64 tile, 256 threads, 4x4 per-thread microtile, BK=16, float4 global+smem loads.
__global__ __launch_bounds__(256) void gemm_bias_kernel(
    const float* __restrict__ A, const float* __restrict__ W,
    const float* __restrict__ bias, float* __restrict__ C,
    int M, int Nc, int K, int relu)
{
    __shared__ float As[16][68];
    __shared__ float Ws[16][68];
    int bm = blockIdx.y * 64;
    int bn = blockIdx.x * 64;
    int tid = threadIdx.x;
    int tx = tid & 15, ty = tid >> 4;
    float acc[4][4];
#pragma unroll
    for (int i = 0; i < 4; i++)
#pragma unroll
        for (int j = 0; j < 4; j++) acc[i][j] = 0.f;

    int lr = tid >> 2;          // 0..63
    int lc = (tid & 3) * 4;     // 0,4,8,12

    for (int k0 = 0; k0 < K; k0 += 16) {
        float4 av = make_float4(0.f, 0.f, 0.f, 0.f);
        int ga = bm + lr;
        if (ga < M) av = *reinterpret_cast<const float4*>(A + (size_t)ga * K + k0 + lc);
        As[lc + 0][lr] = av.x; As[lc + 1][lr] = av.y;
        As[lc + 2][lr] = av.z; As[lc + 3][lr] = av.w;
        float4 wv = make_float4(0.f, 0.f, 0.f, 0.f);
        int gw = bn + lr;
        if (gw < Nc) wv = *reinterpret_cast<const float4*>(W + (size_t)gw * K + k0 + lc);
        Ws[lc + 0][lr] = wv.x; Ws[lc + 1][lr] = wv.y;
        Ws[lc + 2][lr] = wv.z; Ws[lc + 3][lr] = wv.w;
        __syncthreads();
#pragma unroll
        for (int kk = 0; kk < 16; kk++) {
            float4 a = *reinterpret_cast<const float4*>(&As[kk][ty * 4]);
            float4 w = *reinterpret_cast<const float4*>(&Ws[kk][tx * 4]);
            float ar[4] = {a.x, a.y, a.z, a.w};
            float wr[4] = {w.x, w.y, w.z, w.w};
#pragma unroll
            for (int i = 0; i < 4; i++)
#pragma unroll
                for (int j = 0; j < 4; j++) acc[i][j] += ar[i] * wr[j];
        }
        __syncthreads();
    }
#pragma unroll
    for (int i = 0; i < 4; i++) {
        int r = bm + ty * 4 + i;
        if (r >= M) continue;
#pragma unroll
        for (int j = 0; j < 4; j++) {
            int c = bn + tx * 4 + j;
            float vv = acc[i][j] + bias[c];
            if (relu) vv = fmaxf(vv, 0.f);
            C[(size_t)r * Nc + c] = vv;
        }
    }
}

// ---------------- edge phase ----------------
__device__ __forceinline__ void atomicMaxFloat(float* addr, float value) {
    if (value >= 0.f) atomicMax(reinterpret_cast<int*>(addr), __float_as_int(value));
    else atomicMin(reinterpret_cast<unsigned int*>(addr), __float_as_uint(value));
}

// warp per edge: alpha[e,h] = <q[dst,h,:],k[src,h,:]>/sqrt(128); segment max via atomics
__global__ void edge_alpha_kernel(const int* __restrict__ ei) {
    int e = (blockIdx.x * blockDim.x + threadIdx.x) >> 5;
    int lane = threadIdx.x & 31;
    if (e >= EE) return;
    int src = ei[e], dst = ei[EE + e];
    const float4* qr = reinterpret_cast<const float4*>(g_q + (size_t)dst * 512);
    const float4* kr = reinterpret_cast<const float4*>(g_k + (size_t)src * 512);
    float s[4];
#pragma unroll
    for (int h = 0; h < 4; h++) {
        float4 a = qr[h * 32 + lane];
        float4 b = kr[h * 32 + lane];
        s[h] = a.x * b.x + a.y * b.y + a.z * b.z + a.w * b.w;
    }
#pragma unroll
    for (int h = 0; h < 4; h++)
#pragma unroll
        for (int o = 16; o > 0; o >>= 1) s[h] += __shfl_xor_sync(0xffffffffu, s[h], o);
    if (lane == 0) {
#pragma unroll
        for (int h = 0; h < 4; h++) {
            float a = s[h] * 0.0883883476483184f; // 1/sqrt(128)
            g_alpha[(size_t)e * 4 + h] = a;
            atomicMaxFloat(&g_m[dst * 4 + h], a);
        }
    }
}

// thread per (edge,head): ex = exp(alpha - m[dst]); den[dst] += ex
__global__ void edge_exp_kernel(const int* __restrict__ ei) {
    int idx = blockIdx.x * blockDim.x + threadIdx.x;
    if (idx >= EE * 4) return;
    int e = idx >> 2, h = idx & 3;
    int dst = ei[EE + e];
    float ex = expf(g_alpha[idx] - g_m[dst * 4 + h]);
    g_alpha[idx] = ex;
    atomicAdd(&g_den[dst * 4 + h], ex);
}

// warp per edge: agg[dst,h,:] += (ex/den) * v[src,h,:] via red.global.add.v4.f32
__global__ void edge_scatter_kernel(const int* __restrict__ ei) {
    int e = (blockIdx.x * blockDim.x + threadIdx.x) >> 5;
    int lane = threadIdx.x & 31;
    if (e >= EE) return;
    int src = ei[e], dst = ei[EE + e];
    float w[4];
#pragma unroll
    for (int h = 0; h < 4; h++)
        w[h] = g_alpha[(size_t)e * 4 + h] / g_den[dst * 4 + h];
    const float4* vr = reinterpret_cast<const float4*>(g_v + (size_t)src * 512);
    float* ar = g_agg + (size_t)dst * 512;
#pragma unroll
    for (int h = 0; h < 4; h++) {
        float4 vv = vr[h * 32 + lane];
        float* p = ar + h * 128 + lane * 4;
        asm volatile("red.global.add.v4.f32 [%0], {%1, %2, %3, %4};"
                     :: "l"(p), "f"(vv.x * w[h]), "f"(vv.y * w[h]),
                        "f"(vv.z * w[h]), "f"(vv.w * w[h]) : "memory");
    }
}

// ---------------- layernorm kernels (warp per row, float4 lanes) ----------------
__device__ __forceinline__ float4 ln_core(float4 vv, int lane,
                                          const float* __restrict__ g,
                                          const float* __restrict__ b) {
    float sum = vv.x + vv.y + vv.z + vv.w;
    float sq = vv.x * vv.x + vv.y * vv.y + vv.z * vv.z + vv.w * vv.w;
#pragma unroll
    for (int o = 16; o > 0; o >>= 1) {
        sum += __shfl_xor_sync(0xffffffffu, sum, o);
        sq  += __shfl_xor_sync(0xffffffffu, sq, o);
    }
    float mu = sum * (1.f / 128.f);
    float var = sq * (1.f / 128.f) - mu * mu;
    float rstd = rsqrtf(var + 1e-5f);
    float4 gv = reinterpret_cast<const float4*>(g)[lane];
    float4 bv = reinterpret_cast<const float4*>(b)[lane];
    float4 o;
    o.x = (vv.x - mu) * rstd * gv.x + bv.x;
    o.y = (vv.y - mu) * rstd * gv.y + bv.y;
    o.z = (vv.z - mu) * rstd * gv.z + bv.z;
    o.w = (vv.w - mu) * rstd * gv.w + bv.w;
    return o;
}

// x1 = LN(x + mean_h(agg) + skip)
__global__ void ln1_kernel(const float* __restrict__ x,
                           const float* __restrict__ g, const float* __restrict__ b) {
    int row = (blockIdx.x * blockDim.x + threadIdx.x) >> 5;
    int lane = threadIdx.x & 31;
    if (row >= NN) return;
    float4 xv = reinterpret_cast<const float4*>(x + (size_t)row * DD)[lane];
    float4 sv = reinterpret_cast<const float4*>(g_skip + (size_t)row * DD)[lane];
    const float4* ar = reinterpret_cast<const float4*>(g_agg + (size_t)row * 512);
    float4 a0 = ar[lane], a1 = ar[32 + lane], a2 = ar[64 + lane], a3 = ar[96 + lane];
    float4 vv;
    vv.x = xv.x + sv.x + 0.25f * (a0.x + a1.x + a2.x + a3.x);
    vv.y = xv.y + sv.y + 0.25f * (a0.y + a1.y + a2.y + a3.y);
    vv.z = xv.z + sv.z + 0.25f * (a0.z + a1.z + a2.z + a3.z);
    vv.w = xv.w + sv.w + 0.25f * (a0.w + a1.w + a2.w + a3.w);
    float4 o = ln_core(vv, lane, g, b);
    reinterpret_cast<float4*>(g_x1 + (size_t)row * DD)[lane] = o;
}

// out = LN(a + b)
__global__ void ln_add_kernel(const float* __restrict__ a, const float* __restrict__ bb,
                              const float* __restrict__ g, const float* __restrict__ beta,
                              float* __restrict__ out) {
    int row = (blockIdx.x * blockDim.x + threadIdx.x) >> 5;
    int lane = threadIdx.x & 31;
    if (row >= NN) return;
    float4 av = reinterpret_cast<const float4*>(a + (size_t)row * DD)[lane];
    float4 bv = reinterpret_cast<const float4*>(bb + (size_t)row * DD)[lane];
    float4 vv = make_float4(av.x + bv.x, av.y + bv.y, av.z + bv.z, av.w + bv.w);
    float4 o = ln_core(vv, lane, g, beta);
    reinterpret_cast<float4*>(out + (size_t)row * DD)[lane] = o;
}

// ---------------- launch ----------------
static void* sym(const void* s) { void* p = nullptr; cudaGetSymbolAddress(&p, s); return p; }

extern "C" void kernel_launch(void* const* d_in, const int* in_sizes, int n_in,
                              void* d_out, int out_size)
{
    const float* x    = (const float*)d_in[0];
    const float* te   = (const float*)d_in[1];
    const float* gq_w = (const float*)d_in[2];  const float* gq_b = (const float*)d_in[3];
    const float* gk_w = (const float*)d_in[4];  const float* gk_b = (const float*)d_in[5];
    const float* gv_w = (const float*)d_in[6];  const float* gv_b = (const float*)d_in[7];
    const float* gs_w = (const float*)d_in[8];  const float* gs_b = (const float*)d_in[9];
    // mha_wq/bq (10,11) and mha_wk/bk (12,13) are mathematically dead: softmax over
    // a single kv position is exactly 1 regardless of scores.
    const float* wv   = (const float*)d_in[14]; const float* bv   = (const float*)d_in[15];
    const float* wo   = (const float*)d_in[16]; const float* bo   = (const float*)d_in[17];
    const float* w1   = (const float*)d_in[18]; const float* b1   = (const float*)d_in[19];
    const float* w2   = (const float*)d_in[20]; const float* b2   = (const float*)d_in[21];
    const float* ln1g = (const float*)d_in[22]; const float* ln1b = (const float*)d_in[23];
    const float* ln2g = (const float*)d_in[24]; const float* ln2b = (const float*)d_in[25];
    const float* ln3g = (const float*)d_in[26]; const float* ln3b = (const float*)d_in[27];
    const int*   ei   = (const int*)d_in[28];
    float* out = (float*)d_out;

    float* q_p    = (float*)sym(g_q);
    float* k_p    = (float*)sym(g_k);
    float* v_p    = (float*)sym(g_v);
    float* skip_p = (float*)sym(g_skip);
    float* x1_p   = (float*)sym(g_x1);
    float* tv_p   = (float*)sym(g_tv);
    float* tout_p = (float*)sym(g_tout);
    float* x2_p   = (float*)sym(g_x2);
    float* h_p    = (float*)sym(g_h);
    float* ffn_p  = (float*)sym(g_ffn);

    const int MB = (NN + 63) / 64;  // 313 row-tiles

    init_kernel<<<(NN * 512 + 255) / 256, 256>>>();

    // projections (independent of edge phase)
    gemm_bias_kernel<<<dim3(8, MB), 256>>>(x,  gq_w, gq_b, q_p,    NN, 512, 128, 0);
    gemm_bias_kernel<<<dim3(8, MB), 256>>>(x,  gk_w, gk_b, k_p,    NN, 512, 128, 0);
    gemm_bias_kernel<<<dim3(8, MB), 256>>>(x,  gv_w, gv_b, v_p,    NN, 512, 128, 0);
    gemm_bias_kernel<<<dim3(2, MB), 256>>>(x,  gs_w, gs_b, skip_p, NN, 128, 128, 0);
    // temporal branch depends only on temporal_encoding
    gemm_bias_kernel<<<dim3(2, MB), 256>>>(te,   wv, bv, tv_p,   NN, 128, 128, 0);
    gemm_bias_kernel<<<dim3(2, MB), 256>>>(tv_p, wo, bo, tout_p, NN, 128, 128, 0);

    // graph attention (segment softmax over incoming edges)
    edge_alpha_kernel<<<EE / 8, 256>>>(ei);            // warp/edge
    edge_exp_kernel<<<(EE * 4) / 256, 256>>>(ei);      // thread/(edge,head)
    edge_scatter_kernel<<<EE / 8, 256>>>(ei);          // warp/edge, vec4 red

    // x1 = LN(x + mean_h(agg) + skip)
    ln1_kernel<<<(NN + 7) / 8, 256>>>(x, ln1g, ln1b);
    // x2 = LN(x1 + temp_out)
    ln_add_kernel<<<(NN + 7) / 8, 256>>>(x1_p, tout_p, ln2g, ln2b, x2_p);
    // FFN
    gemm_bias_kernel<<<dim3(8, MB), 256>>>(x2_p, w1, b1, h_p,   NN, 512, 128, 1);
    gemm_bias_kernel<<<dim3(2, MB), 256>>>(h_p,  w2, b2, ffn_p, NN, 128, 512, 0);
    // out = LN(x2 + ffn)
    ln_add_kernel<<<(NN + 7) / 8, 256>>>(x2_p, ffn_p, ln3g, ln3b, out);
}

// round 3
// speedup vs baseline: 1.7599x; 1.7599x over previous
#include <cuda_runtime.h>
#include <cuda_bf16.h>
#include <math.h>
#include <math_constants.h>
#include <stdint.h>

#define NN 20000
#define EE 160000
#define DD 128

// ---------------- scratch (static device globals; no allocation) ----------------
__device__ float g_q[NN * 512];
__device__ float g_k[NN * 512];
__device__ float g_v[NN * 512];
__device__ float g_skip[NN * DD];
__device__ float g_alpha[EE * 4];   // alpha, then overwritten with exp values
__device__ float g_m[NN * 4];
__device__ float g_den[NN * 4];
__device__ float g_agg[NN * 512];
__device__ float g_x1[NN * DD];
__device__ float g_tv[NN * DD];
__device__ float g_tout[NN * DD];
__device__ float g_x2[NN * DD];
__device__ float g_h[NN * 512];
__device__ float g_ffn[NN * DD];

// ---------------- init: m=-inf, den=0, agg=0 ----------------
__global__ void init_kernel() {
    int idx = blockIdx.x * blockDim.x + threadIdx.x;
    if (idx < NN * 512) g_agg[idx] = 0.f;
    if (idx < NN * 4) { g_m[idx] = -CUDART_INF_F; g_den[idx] = 0.f; }
}

// ---------------- bf16x3 tensor-core GEMM ----------------
// C[M,Nc] = A[M,K] @ W[Nc,K]^T + bias, optional relu.
// fp32 inputs split into bf16 hi/lo at smem staging; 3-term mma product:
// Ah*Wh + Ah*Wl + Al*Wh (error ~2^-17, vs fp32 ref).
// Block: 128(M) x 64(N) tile, BK=32, 256 threads = 8 warps in 4(m) x 2(n) grid,
// warp tile 32x32 = 2 m-frags x 4 n-frags of m16n8k16.

__device__ __forceinline__ void mma_bf16(float* c, const uint32_t* a, const uint32_t* b) {
    asm volatile(
        "mma.sync.aligned.m16n8k16.row.col.f32.bf16.bf16.f32 "
        "{%0,%1,%2,%3}, {%4,%5,%6,%7}, {%8,%9}, {%0,%1,%2,%3};"
        : "+f"(c[0]), "+f"(c[1]), "+f"(c[2]), "+f"(c[3])
        : "r"(a[0]), "r"(a[1]), "r"(a[2]), "r"(a[3]), "r"(b[0]), "r"(b[1]));
}

__device__ __forceinline__ void split2(float x, float y,
                                       __nv_bfloat162& h, __nv_bfloat162& l) {
    __nv_bfloat16 hx = __float2bfloat16(x);
    __nv_bfloat16 hy = __float2bfloat16(y);
    __nv_bfloat16 lx = __float2bfloat16(x - __bfloat162float(hx));
    __nv_bfloat16 ly = __float2bfloat16(y - __bfloat162float(hy));
    h = __halves2bfloat162(hx, hy);
    l = __halves2bfloat162(lx, ly);
}

#define LDK 40   // padded row length (bf16 elems) -> conflict-free frag loads

__global__ __launch_bounds__(256) void gemm_tc_kernel(
    const float* __restrict__ A, const float* __restrict__ W,
    const float* __restrict__ bias, float* __restrict__ C,
    int M, int Nc, int K, int relu)
{
    __shared__ __nv_bfloat16 As_h[128][LDK];
    __shared__ __nv_bfloat16 As_l[128][LDK];
    __shared__ __nv_bfloat16 Ws_h[64][LDK];
    __shared__ __nv_bfloat16 Ws_l[64][LDK];

    const int tid  = threadIdx.x;
    const int lane = tid & 31;
    const int w    = tid >> 5;
    const int wm   = w & 3;       // 4 m-warps
    const int wn   = w >> 2;      // 2 n-warps
    const int bm   = blockIdx.y * 128;
    const int bn   = blockIdx.x * 64;

    const int qr = lane >> 2;         // 0..7
    const int kq = (lane & 3) * 2;    // 0,2,4,6

    float acc[2][4][4];
#pragma unroll
    for (int i = 0; i < 2; i++)
#pragma unroll
        for (int j = 0; j < 4; j++)
#pragma unroll
            for (int t = 0; t < 4; t++) acc[i][j][t] = 0.f;

    const int sr = tid >> 3;          // 0..31
    const int sc = (tid & 7) * 4;     // 0..28 (k offset, float units)

    for (int k0 = 0; k0 < K; k0 += 32) {
        // ---- stage A: 128 rows x 32 k, fp32 -> bf16 hi/lo ----
#pragma unroll
        for (int it = 0; it < 4; it++) {
            int r = sr + it * 32;
            int ga = bm + r;
            float4 v = make_float4(0.f, 0.f, 0.f, 0.f);
            if (ga < M) v = *reinterpret_cast<const float4*>(A + (size_t)ga * K + k0 + sc);
            __nv_bfloat162 h01, l01, h23, l23;
            split2(v.x, v.y, h01, l01);
            split2(v.z, v.w, h23, l23);
            *reinterpret_cast<__nv_bfloat162*>(&As_h[r][sc])     = h01;
            *reinterpret_cast<__nv_bfloat162*>(&As_h[r][sc + 2]) = h23;
            *reinterpret_cast<__nv_bfloat162*>(&As_l[r][sc])     = l01;
            *reinterpret_cast<__nv_bfloat162*>(&As_l[r][sc + 2]) = l23;
        }
        // ---- stage W: 64 rows x 32 k ----
#pragma unroll
        for (int it = 0; it < 2; it++) {
            int r = sr + it * 32;
            float4 v = *reinterpret_cast<const float4*>(W + (size_t)(bn + r) * K + k0 + sc);
            __nv_bfloat162 h01, l01, h23, l23;
            split2(v.x, v.y, h01, l01);
            split2(v.z, v.w, h23, l23);
            *reinterpret_cast<__nv_bfloat162*>(&Ws_h[r][sc])     = h01;
            *reinterpret_cast<__nv_bfloat162*>(&Ws_h[r][sc + 2]) = h23;
            *reinterpret_cast<__nv_bfloat162*>(&Ws_l[r][sc])     = l01;
            *reinterpret_cast<__nv_bfloat162*>(&Ws_l[r][sc + 2]) = l23;
        }
        __syncthreads();

#pragma unroll
        for (int ks = 0; ks < 32; ks += 16) {
            uint32_t ah[2][4], al[2][4], bh[4][2], bl[4][2];
#pragma unroll
            for (int i = 0; i < 2; i++) {
                int m0 = wm * 32 + i * 16 + qr;
                ah[i][0] = *reinterpret_cast<const uint32_t*>(&As_h[m0    ][ks + kq    ]);
                ah[i][1] = *reinterpret_cast<const uint32_t*>(&As_h[m0 + 8][ks + kq    ]);
                ah[i][2] = *reinterpret_cast<const uint32_t*>(&As_h[m0    ][ks + kq + 8]);
                ah[i][3] = *reinterpret_cast<const uint32_t*>(&As_h[m0 + 8][ks + kq + 8]);
                al[i][0] = *reinterpret_cast<const uint32_t*>(&As_l[m0    ][ks + kq    ]);
                al[i][1] = *reinterpret_cast<const uint32_t*>(&As_l[m0 + 8][ks + kq    ]);
                al[i][2] = *reinterpret_cast<const uint32_t*>(&As_l[m0    ][ks + kq + 8]);
                al[i][3] = *reinterpret_cast<const uint32_t*>(&As_l[m0 + 8][ks + kq + 8]);
            }
#pragma unroll
            for (int j = 0; j < 4; j++) {
                int n0 = wn * 32 + j * 8 + qr;
                bh[j][0] = *reinterpret_cast<const uint32_t*>(&Ws_h[n0][ks + kq    ]);
                bh[j][1] = *reinterpret_cast<const uint32_t*>(&Ws_h[n0][ks + kq + 8]);
                bl[j][0] = *reinterpret_cast<const uint32_t*>(&Ws_l[n0][ks + kq    ]);
                bl[j][1] = *reinterpret_cast<const uint32_t*>(&Ws_l[n0][ks + kq + 8]);
            }
#pragma unroll
            for (int i = 0; i < 2; i++)
#pragma unroll
                for (int j = 0; j < 4; j++) {
                    mma_bf16(acc[i][j], ah[i], bh[j]);
                    mma_bf16(acc[i][j], ah[i], bl[j]);
                    mma_bf16(acc[i][j], al[i], bh[j]);
                }
        }
        __syncthreads();
    }

    // ---- epilogue: bias (+relu), float2 stores ----
#pragma unroll
    for (int i = 0; i < 2; i++) {
        int r0 = bm + wm * 32 + i * 16 + qr;
#pragma unroll
        for (int j = 0; j < 4; j++) {
            int c = bn + wn * 32 + j * 8 + kq;
            float b0 = bias[c], b1 = bias[c + 1];
            float v0 = acc[i][j][0] + b0, v1 = acc[i][j][1] + b1;
            float v2 = acc[i][j][2] + b0, v3 = acc[i][j][3] + b1;
            if (relu) {
                v0 = fmaxf(v0, 0.f); v1 = fmaxf(v1, 0.f);
                v2 = fmaxf(v2, 0.f); v3 = fmaxf(v3, 0.f);
            }
            if (r0 < M)
                *reinterpret_cast<float2*>(C + (size_t)r0 * Nc + c) = make_float2(v0, v1);
            if (r0 + 8 < M)
                *reinterpret_cast<float2*>(C + (size_t)(r0 + 8) * Nc + c) = make_float2(v2, v3);
        }
    }
}

// ---------------- edge phase ----------------
__device__ __forceinline__ void atomicMaxFloat(float* addr, float value) {
    if (value >= 0.f) atomicMax(reinterpret_cast<int*>(addr), __float_as_int(value));
    else atomicMin(reinterpret_cast<unsigned int*>(addr), __float_as_uint(value));
}

// warp per edge: alpha[e,h] = <q[dst,h,:],k[src,h,:]>/sqrt(128); segment max via atomics
__global__ void edge_alpha_kernel(const int* __restrict__ ei) {
    int e = (blockIdx.x * blockDim.x + threadIdx.x) >> 5;
    int lane = threadIdx.x & 31;
    if (e >= EE) return;
    int src = ei[e], dst = ei[EE + e];
    const float4* qr = reinterpret_cast<const float4*>(g_q + (size_t)dst * 512);
    const float4* kr = reinterpret_cast<const float4*>(g_k + (size_t)src * 512);
    float s[4];
#pragma unroll
    for (int h = 0; h < 4; h++) {
        float4 a = qr[h * 32 + lane];
        float4 b = kr[h * 32 + lane];
        s[h] = a.x * b.x + a.y * b.y + a.z * b.z + a.w * b.w;
    }
#pragma unroll
    for (int h = 0; h < 4; h++)
#pragma unroll
        for (int o = 16; o > 0; o >>= 1) s[h] += __shfl_xor_sync(0xffffffffu, s[h], o);
    if (lane == 0) {
#pragma unroll
        for (int h = 0; h < 4; h++) {
            float a = s[h] * 0.0883883476483184f; // 1/sqrt(128)
            g_alpha[(size_t)e * 4 + h] = a;
            atomicMaxFloat(&g_m[dst * 4 + h], a);
        }
    }
}

// thread per (edge,head): ex = exp(alpha - m[dst]); den[dst] += ex
__global__ void edge_exp_kernel(const int* __restrict__ ei) {
    int idx = blockIdx.x * blockDim.x + threadIdx.x;
    if (idx >= EE * 4) return;
    int e = idx >> 2, h = idx & 3;
    int dst = ei[EE + e];
    float ex = expf(g_alpha[idx] - g_m[dst * 4 + h]);
    g_alpha[idx] = ex;
    atomicAdd(&g_den[dst * 4 + h], ex);
}

// warp per edge: agg[dst,h,:] += (ex/den) * v[src,h,:] via red.global.add.v4.f32
__global__ void edge_scatter_kernel(const int* __restrict__ ei) {
    int e = (blockIdx.x * blockDim.x + threadIdx.x) >> 5;
    int lane = threadIdx.x & 31;
    if (e >= EE) return;
    int src = ei[e], dst = ei[EE + e];
    float w[4];
#pragma unroll
    for (int h = 0; h < 4; h++)
        w[h] = g_alpha[(size_t)e * 4 + h] / g_den[dst * 4 + h];
    const float4* vr = reinterpret_cast<const float4*>(g_v + (size_t)src * 512);
    float* ar = g_agg + (size_t)dst * 512;
#pragma unroll
    for (int h = 0; h < 4; h++) {
        float4 vv = vr[h * 32 + lane];
        float* p = ar + h * 128 + lane * 4;
        asm volatile("red.global.add.v4.f32 [%0], {%1, %2, %3, %4};"
                     :: "l"(p), "f"(vv.x * w[h]), "f"(vv.y * w[h]),
                        "f"(vv.z * w[h]), "f"(vv.w * w[h]) : "memory");
    }
}

// ---------------- layernorm kernels (warp per row, float4 lanes) ----------------
__device__ __forceinline__ float4 ln_core(float4 vv, int lane,
                                          const float* __restrict__ g,
                                          const float* __restrict__ b) {
    float sum = vv.x + vv.y + vv.z + vv.w;
    float sq = vv.x * vv.x + vv.y * vv.y + vv.z * vv.z + vv.w * vv.w;
#pragma unroll
    for (int o = 16; o > 0; o >>= 1) {
        sum += __shfl_xor_sync(0xffffffffu, sum, o);
        sq  += __shfl_xor_sync(0xffffffffu, sq, o);
    }
    float mu = sum * (1.f / 128.f);
    float var = sq * (1.f / 128.f) - mu * mu;
    float rstd = rsqrtf(var + 1e-5f);
    float4 gv = reinterpret_cast<const float4*>(g)[lane];
    float4 bv = reinterpret_cast<const float4*>(b)[lane];
    float4 o;
    o.x = (vv.x - mu) * rstd * gv.x + bv.x;
    o.y = (vv.y - mu) * rstd * gv.y + bv.y;
    o.z = (vv.z - mu) * rstd * gv.z + bv.z;
    o.w = (vv.w - mu) * rstd * gv.w + bv.w;
    return o;
}

// x1 = LN(x + mean_h(agg) + skip)
__global__ void ln1_kernel(const float* __restrict__ x,
                           const float* __restrict__ g, const float* __restrict__ b) {
    int row = (blockIdx.x * blockDim.x + threadIdx.x) >> 5;
    int lane = threadIdx.x & 31;
    if (row >= NN) return;
    float4 xv = reinterpret_cast<const float4*>(x + (size_t)row * DD)[lane];
    float4 sv = reinterpret_cast<const float4*>(g_skip + (size_t)row * DD)[lane];
    const float4* ar = reinterpret_cast<const float4*>(g_agg + (size_t)row * 512);
    float4 a0 = ar[lane], a1 = ar[32 + lane], a2 = ar[64 + lane], a3 = ar[96 + lane];
    float4 vv;
    vv.x = xv.x + sv.x + 0.25f * (a0.x + a1.x + a2.x + a3.x);
    vv.y = xv.y + sv.y + 0.25f * (a0.y + a1.y + a2.y + a3.y);
    vv.z = xv.z + sv.z + 0.25f * (a0.z + a1.z + a2.z + a3.z);
    vv.w = xv.w + sv.w + 0.25f * (a0.w + a1.w + a2.w + a3.w);
    float4 o = ln_core(vv, lane, g, b);
    reinterpret_cast<float4*>(g_x1 + (size_t)row * DD)[lane] = o;
}

// out = LN(a + b)
__global__ void ln_add_kernel(const float* __restrict__ a, const float* __restrict__ bb,
                              const float* __restrict__ g, const float* __restrict__ beta,
                              float* __restrict__ out) {
    int row = (blockIdx.x * blockDim.x + threadIdx.x) >> 5;
    int lane = threadIdx.x & 31;
    if (row >= NN) return;
    float4 av = reinterpret_cast<const float4*>(a + (size_t)row * DD)[lane];
    float4 bv = reinterpret_cast<const float4*>(bb + (size_t)row * DD)[lane];
    float4 vv = make_float4(av.x + bv.x, av.y + bv.y, av.z + bv.z, av.w + bv.w);
    float4 o = ln_core(vv, lane, g, beta);
    reinterpret_cast<float4*>(out + (size_t)row * DD)[lane] = o;
}

// ---------------- launch ----------------
static void* sym(const void* s) { void* p = nullptr; cudaGetSymbolAddress(&p, s); return p; }

extern "C" void kernel_launch(void* const* d_in, const int* in_sizes, int n_in,
                              void* d_out, int out_size)
{
    const float* x    = (const float*)d_in[0];
    const float* te   = (const float*)d_in[1];
    const float* gq_w = (const float*)d_in[2];  const float* gq_b = (const float*)d_in[3];
    const float* gk_w = (const float*)d_in[4];  const float* gk_b = (const float*)d_in[5];
    const float* gv_w = (const float*)d_in[6];  const float* gv_b = (const float*)d_in[7];
    const float* gs_w = (const float*)d_in[8];  const float* gs_b = (const float*)d_in[9];
    // mha_wq/bq (10,11) and mha_wk/bk (12,13) are mathematically dead: softmax over
    // a single kv position is exactly 1 regardless of scores.
    const float* wv   = (const float*)d_in[14]; const float* bv   = (const float*)d_in[15];
    const float* wo   = (const float*)d_in[16]; const float* bo   = (const float*)d_in[17];
    const float* w1   = (const float*)d_in[18]; const float* b1   = (const float*)d_in[19];
    const float* w2   = (const float*)d_in[20]; const float* b2   = (const float*)d_in[21];
    const float* ln1g = (const float*)d_in[22]; const float* ln1b = (const float*)d_in[23];
    const float* ln2g = (const float*)d_in[24]; const float* ln2b = (const float*)d_in[25];
    const float* ln3g = (const float*)d_in[26]; const float* ln3b = (const float*)d_in[27];
    const int*   ei   = (const int*)d_in[28];
    float* out = (float*)d_out;

    float* q_p    = (float*)sym(g_q);
    float* k_p    = (float*)sym(g_k);
    float* v_p    = (float*)sym(g_v);
    float* skip_p = (float*)sym(g_skip);
    float* x1_p   = (float*)sym(g_x1);
    float* tv_p   = (float*)sym(g_tv);
    float* tout_p = (float*)sym(g_tout);
    float* x2_p   = (float*)sym(g_x2);
    float* h_p    = (float*)sym(g_h);
    float* ffn_p  = (float*)sym(g_ffn);

    const int MB = (NN + 127) / 128;  // 157 row-tiles

    init_kernel<<<(NN * 512 + 255) / 256, 256>>>();

    // projections (independent of edge phase) — bf16x3 tensor-core GEMM
    gemm_tc_kernel<<<dim3(8, MB), 256>>>(x,  gq_w, gq_b, q_p,    NN, 512, 128, 0);
    gemm_tc_kernel<<<dim3(8, MB), 256>>>(x,  gk_w, gk_b, k_p,    NN, 512, 128, 0);
    gemm_tc_kernel<<<dim3(8, MB), 256>>>(x,  gv_w, gv_b, v_p,    NN, 512, 128, 0);
    gemm_tc_kernel<<<dim3(2, MB), 256>>>(x,  gs_w, gs_b, skip_p, NN, 128, 128, 0);
    // temporal branch depends only on temporal_encoding
    gemm_tc_kernel<<<dim3(2, MB), 256>>>(te,   wv, bv, tv_p,   NN, 128, 128, 0);
    gemm_tc_kernel<<<dim3(2, MB), 256>>>(tv_p, wo, bo, tout_p, NN, 128, 128, 0);

    // graph attention (segment softmax over incoming edges)
    edge_alpha_kernel<<<EE / 8, 256>>>(ei);            // warp/edge
    edge_exp_kernel<<<(EE * 4) / 256, 256>>>(ei);      // thread/(edge,head)
    edge_scatter_kernel<<<EE / 8, 256>>>(ei);          // warp/edge, vec4 red

    // x1 = LN(x + mean_h(agg) + skip)
    ln1_kernel<<<(NN + 7) / 8, 256>>>(x, ln1g, ln1b);
    // x2 = LN(x1 + temp_out)
    ln_add_kernel<<<(NN + 7) / 8, 256>>>(x1_p, tout_p, ln2g, ln2b, x2_p);
    // FFN
    gemm_tc_kernel<<<dim3(8, MB), 256>>>(x2_p, w1, b1, h_p,   NN, 512, 128, 1);
    gemm_tc_kernel<<<dim3(2, MB), 256>>>(h_p,  w2, b2, ffn_p, NN, 128, 512, 0);
    // out = LN(x2 + ffn)
    ln_add_kernel<<<(NN + 7) / 8, 256>>>(x2_p, ffn_p, ln3g, ln3b, out);
}